// round 12
// baseline (speedup 1.0000x reference)
#include <cuda_runtime.h>

#define TCOLS 4096
#define BROWS 4096
#define NT 128
#define NWARP 4
#define NCTA (2 * BROWS)
#define FULL 0xffffffffu

__device__ float2   g_resP[BROWS];   // {sbp, dbp} per preds row
__device__ float2   g_resL[BROWS];   // {sbp, dbp} per labels row
__device__ unsigned g_done;          // zero-init; reset by last CTA

__device__ __forceinline__ float warp_sum(float v) {
    #pragma unroll
    for (int o = 16; o; o >>= 1) v += __shfl_xor_sync(FULL, v, o);
    return v;
}

__global__ __launch_bounds__(NT, 8)
void pv_kernel(const float* __restrict__ preds,
               const float* __restrict__ labels,
               float* __restrict__ out) {
    __shared__ float sred[4][NWARP];
    __shared__ bool  amLast;

    const int tid  = threadIdx.x;
    const int lane = tid & 31;
    const int wid  = tid >> 5;
    const int arr  = blockIdx.x >> 12;          // 0 = preds, 1 = labels
    const int row  = blockIdx.x & (BROWS - 1);

    const float* rowp = (arr ? labels : preds) + ((size_t)row << 12);
    const int wb = wid << 10;                   // 1024 elements per warp
    const float4* g4 = (const float4*)(rowp + wb);

    // ---- Load lane's 32 elements (8 coalesced float4 groups) ----
    float v[32];
    #pragma unroll
    for (int g = 0; g < 8; g++) {
        float4 a = g4[g * 32 + lane];
        v[4*g] = a.x; v[4*g+1] = a.y; v[4*g+2] = a.z; v[4*g+3] = a.w;
    }

    // Segment-edge values (row-end centers masked off explicitly below).
    float edge_l = 0.f, edge_r = 0.f;
    if (lane == 31) edge_l = rowp[wb ? wb - 1 : 0];
    if (lane == 0)  edge_r = rowp[wb + 1024 < TCOLS ? wb + 1024 : TCOLS - 1];

    const int upidx = (lane + 31) & 31;
    const int dnidx = (lane + 1) & 31;
    const bool is31 = (lane == 31);
    const bool is0  = (lane == 0);
    const bool rowStart = is0  && (wb == 0);
    const bool rowEnd   = is31 && (wb + 1024 == TCOLS);

    // ---- Pass 1: sign-packed peak/valley detection, 2-way split accumulators ----
    float psA = 0.f, psB = 0.f, vsA = 0.f, vsB = 0.f;
    unsigned pkm = 0, vym = 0;
    float prevw = edge_l;
    #pragma unroll
    for (int g = 0; g < 8; g++) {
        const float cx = v[4*g], cy = v[4*g+1], cz = v[4*g+2], cw = v[4*g+3];
        float bl = is31 ? prevw : cw;
        float lv = __shfl_sync(FULL, bl, upidx);     // lane i <- lane i-1
        float nx = (g < 7) ? v[4*g+4] : edge_r;
        float br = is0 ? nx : cx;
        float rv = __shfl_sync(FULL, br, dnidx);     // lane i <- lane i+1
        prevw = cw;

        const int i0 = __float_as_int(cx - lv);
        const int i1 = __float_as_int(cy - cx);
        const int i2 = __float_as_int(cz - cy);
        const int i3 = __float_as_int(cw - cz);
        const int i4 = __float_as_int(rv - cw);

        unsigned a01 = __byte_perm(i0, i1, 0x0073);
        unsigned a23 = __byte_perm(i2, i3, 0x7300);
        unsigned s   = __byte_perm(a01, a23, 0x7610);
        unsigned sn  = __byte_perm(s,   i4, 0x7321);
        unsigned pkb = ~s & sn;      // byte k bit7: d_k>0 && d_{k+1}<0
        unsigned vyb = s & ~sn;      // byte k bit7: d_k<0 && d_{k+1}>0

        if (g == 0 && rowStart) { pkb &= ~0x80u;       vyb &= ~0x80u; }
        if (g == 7 && rowEnd)   { pkb &= 0x7fffffffu;  vyb &= 0x7fffffffu; }

        // Split accumulation: centers 0,2 -> A; 1,3 -> B (independent chains)
        if (pkb & 0x00000080u) { psA += cx; pkm |= 1u << (4*g + 0); }
        if (vyb & 0x00000080u) { vsA += cx; vym |= 1u << (4*g + 0); }
        if (pkb & 0x00008000u) { psB += cy; pkm |= 1u << (4*g + 1); }
        if (vyb & 0x00008000u) { vsB += cy; vym |= 1u << (4*g + 1); }
        if (pkb & 0x00800000u) { psA += cz; pkm |= 1u << (4*g + 2); }
        if (vyb & 0x00800000u) { vsA += cz; vym |= 1u << (4*g + 2); }
        if (pkb & 0x80000000u) { psB += cw; pkm |= 1u << (4*g + 3); }
        if (vyb & 0x80000000u) { vsB += cw; vym |= 1u << (4*g + 3); }
    }

    float psum = warp_sum(psA + psB);
    float vsum = warp_sum(vsA + vsB);
    int pcnt = __reduce_add_sync(FULL, __popc(pkm));
    int vcnt = __reduce_add_sync(FULL, __popc(vym));
    if (lane == 0) {
        sred[0][wid] = psum;
        sred[1][wid] = vsum;
        sred[2][wid] = (float)pcnt;
        sred[3][wid] = (float)vcnt;
    }
    __syncthreads();
    const float pm = (sred[0][0] + sred[0][1] + sred[0][2] + sred[0][3])
                   / (sred[2][0] + sred[2][1] + sred[2][2] + sred[2][3]);
    const float vm = (sred[1][0] + sred[1][1] + sred[1][2] + sred[1][3])
                   / (sred[3][0] + sred[3][1] + sred[3][2] + sred[3][3]);
    __syncthreads();   // sred reuse

    // ---- Pass 2: thresholded masked means; 2-way split sums, int counts ----
    float s0A = 0.f, s0B = 0.f, s1A = 0.f, s1B = 0.f;
    int   c0A = 0,   c0B = 0,   c1A = 0,   c1B = 0;
    #pragma unroll
    for (int k = 0; k < 32; k += 2) {
        const unsigned bitA = 1u << k;
        const unsigned bitB = 1u << (k + 1);
        const float va = v[k], vb = v[k + 1];
        if ((pkm & bitA) && va >= pm) { s0A += va; c0A++; }
        if ((vym & bitA) && va <= vm) { s1A += va; c1A++; }
        if ((pkm & bitB) && vb >= pm) { s0B += vb; c0B++; }
        if ((vym & bitB) && vb <= vm) { s1B += vb; c1B++; }
    }
    float s0 = warp_sum(s0A + s0B);
    float s1 = warp_sum(s1A + s1B);
    int   c0 = __reduce_add_sync(FULL, c0A + c0B);
    int   c1 = __reduce_add_sync(FULL, c1A + c1B);
    if (lane == 0) {
        sred[0][wid] = s0;
        sred[1][wid] = s1;
        sred[2][wid] = (float)c0;
        sred[3][wid] = (float)c1;
    }
    __syncthreads();

    if (tid == 0) {
        float a0 = sred[0][0] + sred[0][1] + sred[0][2] + sred[0][3];
        float a1 = sred[1][0] + sred[1][1] + sred[1][2] + sred[1][3];
        float a2 = sred[2][0] + sred[2][1] + sred[2][2] + sred[2][3];
        float a3 = sred[3][0] + sred[3][1] + sred[3][2] + sred[3][3];
        float2 r = make_float2(a0 / a2, a1 / a3);
        if (arr) g_resL[row] = r; else g_resP[row] = r;
        __threadfence();
        amLast = (atomicAdd(&g_done, 1u) == (unsigned)(NCTA - 1));
    }
    __syncthreads();

    // ---- Last CTA: combine all per-row results into the scalar loss ----
    if (amLast) {
        float acc = 0.f;
        #pragma unroll
        for (int q = 0; q < BROWS / NT; q++) {
            int r = tid + q * NT;
            float2 p = g_resP[r];
            float2 l = g_resL[r];
            float d0 = p.x - l.x;
            float d1 = p.y - l.y;
            acc += d0 * d0 + d1 * d1;
        }
        acc = warp_sum(acc);
        if (lane == 0) sred[0][wid] = acc;
        __syncthreads();
        if (tid == 0) {
            out[0] = (sred[0][0] + sred[0][1] + sred[0][2] + sred[0][3])
                   / (float)(BROWS * 2);
            g_done = 0;
        }
    }
}

extern "C" void kernel_launch(void* const* d_in, const int* in_sizes, int n_in,
                              void* d_out, int out_size) {
    const float* preds  = (const float*)d_in[0];
    const float* labels = (const float*)d_in[1];
    pv_kernel<<<NCTA, NT>>>(preds, labels, (float*)d_out);
}

// round 13
// speedup vs baseline: 1.0085x; 1.0085x over previous
#include <cuda_runtime.h>

#define TCOLS 4096
#define BROWS 4096
#define NT 128
#define NWARP 4
#define NCTA (2 * BROWS)
#define FULL 0xffffffffu

// Padded SMEM layout: +4 floats per 32 -> conflict-free per-thread blocks.
#define SPAD(i) ((i) + 4 * ((i) >> 5))
#define SVLEN 4608   // SPAD(4095)+1 = 4604, rounded up

__device__ float2   g_resP[BROWS];
__device__ float2   g_resL[BROWS];
__device__ unsigned g_done;

__device__ __forceinline__ float warp_sum(float v) {
    #pragma unroll
    for (int o = 16; o; o >>= 1) v += __shfl_xor_sync(FULL, v, o);
    return v;
}

__global__ __launch_bounds__(NT, 10)
void pv_kernel(const float* __restrict__ preds,
               const float* __restrict__ labels,
               float* __restrict__ out) {
    __shared__ float sv[SVLEN];
    __shared__ float sred[4][NWARP];
    __shared__ bool  amLast;

    const int tid  = threadIdx.x;
    const int lane = tid & 31;
    const int wid  = tid >> 5;
    const int arr  = blockIdx.x >> 12;          // 0 = preds, 1 = labels
    const int row  = blockIdx.x & (BROWS - 1);

    const float* rowp = (arr ? labels : preds) + ((size_t)row << 12);
    const float4* g4  = (const float4*)rowp;

    // ---- Stage row into padded SMEM (coalesced LDG.128 -> STS.128) ----
    {
        float4 t[8];
        #pragma unroll
        for (int g = 0; g < 8; g++) t[g] = g4[g * NT + tid];
        #pragma unroll
        for (int g = 0; g < 8; g++) {
            const int idx = (g * NT + tid) * 4;
            *(float4*)(sv + SPAD(idx)) = t[g];
        }
    }
    __syncthreads();

    // Thread's contiguous 32-element block starts at element tb.
    const int tb = tid * 32;
    const float4* sv4 = (const float4*)(sv + tid * 36);   // SPAD(tb) = tid*36

    // Neighbors (clamped at row edges; those centers are mask-cleared below).
    const float prev0 = (tid == 0)    ? sv[0]          : sv[SPAD(tb - 1)];
    const float nb    = (tid == NT-1) ? sv[SPAD(4095)] : sv[(tid + 1) * 36];

    // ---- Pass 1: sign-packed peak/valley detection (no shuffles) ----
    float psum = 0.f, vsum = 0.f;
    unsigned pkm = 0, vym = 0;
    float prevw = prev0;
    float4 c = sv4[0];
    #pragma unroll
    for (int j = 0; j < 8; j++) {
        float4 n;
        float nextx;
        if (j < 7) { n = sv4[j + 1]; nextx = n.x; }
        else       { nextx = nb; }

        const int i0 = __float_as_int(c.x - prevw);
        const int i1 = __float_as_int(c.y - c.x);
        const int i2 = __float_as_int(c.z - c.y);
        const int i3 = __float_as_int(c.w - c.z);
        const int i4 = __float_as_int(nextx - c.w);

        unsigned a01 = __byte_perm(i0, i1, 0x0073);
        unsigned a23 = __byte_perm(i2, i3, 0x7300);
        unsigned s   = __byte_perm(a01, a23, 0x7610);
        unsigned sn  = __byte_perm(s,   i4, 0x7321);
        unsigned pkb = ~s & sn;      // byte k bit7: d_k>0 && d_{k+1}<0
        unsigned vyb = s & ~sn;      // byte k bit7: d_k<0 && d_{k+1}>0

        if (pkb & 0x00000080u) { psum += c.x; pkm |= 1u << (4*j + 0); }
        if (vyb & 0x00000080u) { vsum += c.x; vym |= 1u << (4*j + 0); }
        if (pkb & 0x00008000u) { psum += c.y; pkm |= 1u << (4*j + 1); }
        if (vyb & 0x00008000u) { vsum += c.y; vym |= 1u << (4*j + 1); }
        if (pkb & 0x00800000u) { psum += c.z; pkm |= 1u << (4*j + 2); }
        if (vyb & 0x00800000u) { vsum += c.z; vym |= 1u << (4*j + 2); }
        if (pkb & 0x80000000u) { psum += c.w; pkm |= 1u << (4*j + 3); }
        if (vyb & 0x80000000u) { vsum += c.w; vym |= 1u << (4*j + 3); }

        prevw = c.w;
        if (j < 7) c = n;
    }

    // Row-edge centers (elements 0 and TCOLS-1) are not valid centers.
    if (tid == 0) {
        if (pkm & 1u) { psum -= sv[0]; pkm &= ~1u; }
        if (vym & 1u) { vsum -= sv[0]; vym &= ~1u; }
    }
    if (tid == NT - 1) {
        const unsigned top = 0x80000000u;
        if (pkm & top) { psum -= sv[SPAD(4095)]; pkm &= ~top; }
        if (vym & top) { vsum -= sv[SPAD(4095)]; vym &= ~top; }
    }

    psum = warp_sum(psum);
    vsum = warp_sum(vsum);
    int pcnt = __reduce_add_sync(FULL, __popc(pkm));
    int vcnt = __reduce_add_sync(FULL, __popc(vym));
    if (lane == 0) {
        sred[0][wid] = psum;
        sred[1][wid] = vsum;
        sred[2][wid] = (float)pcnt;
        sred[3][wid] = (float)vcnt;
    }
    __syncthreads();
    const float pm = (sred[0][0] + sred[0][1] + sred[0][2] + sred[0][3])
                   / (sred[2][0] + sred[2][1] + sred[2][2] + sred[2][3]);
    const float vm = (sred[1][0] + sred[1][1] + sred[1][2] + sred[1][3])
                   / (sred[3][0] + sred[3][1] + sred[3][2] + sred[3][3]);
    __syncthreads();

    // ---- Pass 2: thresholded masked means, re-read SMEM ----
    float s0 = 0.f, s1 = 0.f;
    int   c0 = 0,   c1 = 0;
    #pragma unroll
    for (int j = 0; j < 8; j++) {
        const float4 a = sv4[j];
        const unsigned b0 = 1u << (4*j + 0), b1 = 1u << (4*j + 1);
        const unsigned b2 = 1u << (4*j + 2), b3 = 1u << (4*j + 3);
        if ((pkm & b0) && a.x >= pm) { s0 += a.x; c0++; }
        if ((vym & b0) && a.x <= vm) { s1 += a.x; c1++; }
        if ((pkm & b1) && a.y >= pm) { s0 += a.y; c0++; }
        if ((vym & b1) && a.y <= vm) { s1 += a.y; c1++; }
        if ((pkm & b2) && a.z >= pm) { s0 += a.z; c0++; }
        if ((vym & b2) && a.z <= vm) { s1 += a.z; c1++; }
        if ((pkm & b3) && a.w >= pm) { s0 += a.w; c0++; }
        if ((vym & b3) && a.w <= vm) { s1 += a.w; c1++; }
    }
    s0 = warp_sum(s0);
    s1 = warp_sum(s1);
    c0 = __reduce_add_sync(FULL, c0);
    c1 = __reduce_add_sync(FULL, c1);
    if (lane == 0) {
        sred[0][wid] = s0;
        sred[1][wid] = s1;
        sred[2][wid] = (float)c0;
        sred[3][wid] = (float)c1;
    }
    __syncthreads();

    if (tid == 0) {
        float a0 = sred[0][0] + sred[0][1] + sred[0][2] + sred[0][3];
        float a1 = sred[1][0] + sred[1][1] + sred[1][2] + sred[1][3];
        float a2 = sred[2][0] + sred[2][1] + sred[2][2] + sred[2][3];
        float a3 = sred[3][0] + sred[3][1] + sred[3][2] + sred[3][3];
        float2 r = make_float2(a0 / a2, a1 / a3);
        if (arr) g_resL[row] = r; else g_resP[row] = r;
        __threadfence();
        amLast = (atomicAdd(&g_done, 1u) == (unsigned)(NCTA - 1));
    }
    __syncthreads();

    // ---- Last CTA: combine per-row results into the scalar loss ----
    if (amLast) {
        float acc = 0.f;
        #pragma unroll
        for (int q = 0; q < BROWS / NT; q++) {
            int r = tid + q * NT;
            float2 p = g_resP[r];
            float2 l = g_resL[r];
            float d0 = p.x - l.x;
            float d1 = p.y - l.y;
            acc += d0 * d0 + d1 * d1;
        }
        acc = warp_sum(acc);
        if (lane == 0) sred[0][wid] = acc;
        __syncthreads();
        if (tid == 0) {
            out[0] = (sred[0][0] + sred[0][1] + sred[0][2] + sred[0][3])
                   / (float)(BROWS * 2);
            g_done = 0;
        }
    }
}

extern "C" void kernel_launch(void* const* d_in, const int* in_sizes, int n_in,
                              void* d_out, int out_size) {
    const float* preds  = (const float*)d_in[0];
    const float* labels = (const float*)d_in[1];
    pv_kernel<<<NCTA, NT>>>(preds, labels, (float*)d_out);
}

// round 14
// speedup vs baseline: 1.0530x; 1.0441x over previous
#include <cuda_runtime.h>

#define TCOLS 4096
#define BROWS 4096
#define NT 128
#define NWARP 4
#define NCTA (2 * BROWS)
#define FULL 0xffffffffu

__device__ float2   g_resP[BROWS];   // {sbp, dbp} per preds row
__device__ float2   g_resL[BROWS];   // {sbp, dbp} per labels row
__device__ unsigned g_done;          // zero-init; reset by last CTA

__device__ __forceinline__ float warp_sum(float v) {
    #pragma unroll
    for (int o = 16; o; o >>= 1) v += __shfl_xor_sync(FULL, v, o);
    return v;
}

__global__ __launch_bounds__(NT, 8)
void pv_kernel(const float* __restrict__ preds,
               const float* __restrict__ labels,
               float* __restrict__ out) {
    __shared__ float sred[4][NWARP];
    __shared__ float smeans[2];
    __shared__ bool  amLast;

    const int tid  = threadIdx.x;
    const int lane = tid & 31;
    const int wid  = tid >> 5;
    const int arr  = blockIdx.x >> 12;          // 0 = preds, 1 = labels
    const int row  = blockIdx.x & (BROWS - 1);

    const float* rowp = (arr ? labels : preds) + ((size_t)row << 12);
    const int wb = wid << 10;                   // 1024 elements per warp
    const float4* g4 = (const float4*)(rowp + wb);

    // ---- Load lane's 32 elements (8 coalesced float4 groups) ----
    float v[32];
    #pragma unroll
    for (int g = 0; g < 8; g++) {
        float4 a = g4[g * 32 + lane];
        v[4*g] = a.x; v[4*g+1] = a.y; v[4*g+2] = a.z; v[4*g+3] = a.w;
    }

    // Segment-edge values (row-end centers masked off explicitly below).
    float edge_l = 0.f, edge_r = 0.f;
    if (lane == 31) edge_l = rowp[wb ? wb - 1 : 0];
    if (lane == 0)  edge_r = rowp[wb + 1024 < TCOLS ? wb + 1024 : TCOLS - 1];

    const int upidx = (lane + 31) & 31;
    const int dnidx = (lane + 1) & 31;
    const bool is31 = (lane == 31);
    const bool is0  = (lane == 0);
    const bool rowStart = is0  && (wb == 0);
    const bool rowEnd   = is31 && (wb + 1024 == TCOLS);

    // ---- Pass 1: sign-packed peak/valley detection ----
    float psum = 0.f, vsum = 0.f;
    unsigned pkm = 0, vym = 0;
    float prevw = edge_l;
    #pragma unroll
    for (int g = 0; g < 8; g++) {
        const float cx = v[4*g], cy = v[4*g+1], cz = v[4*g+2], cw = v[4*g+3];
        float bl = is31 ? prevw : cw;
        float lv = __shfl_sync(FULL, bl, upidx);     // lane i <- lane i-1
        float nx = (g < 7) ? v[4*g+4] : edge_r;
        float br = is0 ? nx : cx;
        float rv = __shfl_sync(FULL, br, dnidx);     // lane i <- lane i+1
        prevw = cw;

        const int i0 = __float_as_int(cx - lv);
        const int i1 = __float_as_int(cy - cx);
        const int i2 = __float_as_int(cz - cy);
        const int i3 = __float_as_int(cw - cz);
        const int i4 = __float_as_int(rv - cw);

        unsigned a01 = __byte_perm(i0, i1, 0x0073);
        unsigned a23 = __byte_perm(i2, i3, 0x7300);
        unsigned s   = __byte_perm(a01, a23, 0x7610);
        unsigned sn  = __byte_perm(s,   i4, 0x7321);
        unsigned pkb = ~s & sn;      // byte k bit7: d_k>0 && d_{k+1}<0
        unsigned vyb = s & ~sn;      // byte k bit7: d_k<0 && d_{k+1}>0

        if (g == 0 && rowStart) { pkb &= ~0x80u;       vyb &= ~0x80u; }
        if (g == 7 && rowEnd)   { pkb &= 0x7fffffffu;  vyb &= 0x7fffffffu; }

        // += with unique bits == |= ; lets ptxas alternate IMAD/IADD3 pipes.
        if (pkb & 0x00000080u) { psum += cx; pkm += (1u << (4*g + 0)); }
        if (vyb & 0x00000080u) { vsum += cx; vym += (1u << (4*g + 0)); }
        if (pkb & 0x00008000u) { psum += cy; pkm += (1u << (4*g + 1)); }
        if (vyb & 0x00008000u) { vsum += cy; vym += (1u << (4*g + 1)); }
        if (pkb & 0x00800000u) { psum += cz; pkm += (1u << (4*g + 2)); }
        if (vyb & 0x00800000u) { vsum += cz; vym += (1u << (4*g + 2)); }
        if (pkb & 0x80000000u) { psum += cw; pkm += (1u << (4*g + 3)); }
        if (vyb & 0x80000000u) { vsum += cw; vym += (1u << (4*g + 3)); }
    }

    psum = warp_sum(psum);
    vsum = warp_sum(vsum);
    int pcnt = __reduce_add_sync(FULL, __popc(pkm));
    int vcnt = __reduce_add_sync(FULL, __popc(vym));
    if (lane == 0) {
        sred[0][wid] = psum;
        sred[1][wid] = vsum;
        sred[2][wid] = (float)pcnt;
        sred[3][wid] = (float)vcnt;
    }
    __syncthreads();
    if (tid == 0) {
        float a0 = sred[0][0] + sred[0][1] + sred[0][2] + sred[0][3];
        float a1 = sred[1][0] + sred[1][1] + sred[1][2] + sred[1][3];
        float a2 = sred[2][0] + sred[2][1] + sred[2][2] + sred[2][3];
        float a3 = sred[3][0] + sred[3][1] + sred[3][2] + sred[3][3];
        smeans[0] = a0 / a2;
        smeans[1] = a1 / a3;
    }
    __syncthreads();
    const float pm = smeans[0];
    const float vm = smeans[1];

    // ---- Pass 2: thresholded masked means; counts via result-mask popc ----
    float s0 = 0.f, s1 = 0.f;
    unsigned m0 = 0, m1 = 0;
    #pragma unroll
    for (int k = 0; k < 32; k++) {
        const unsigned bit = 1u << k;
        if ((pkm & bit) && v[k] >= pm) { s0 += v[k]; m0 += bit; }
        if ((vym & bit) && v[k] <= vm) { s1 += v[k]; m1 += bit; }
    }
    s0 = warp_sum(s0);
    s1 = warp_sum(s1);
    int c0 = __reduce_add_sync(FULL, __popc(m0));
    int c1 = __reduce_add_sync(FULL, __popc(m1));
    if (lane == 0) {
        sred[0][wid] = s0;
        sred[1][wid] = s1;
        sred[2][wid] = (float)c0;
        sred[3][wid] = (float)c1;
    }
    __syncthreads();

    if (tid == 0) {
        float a0 = sred[0][0] + sred[0][1] + sred[0][2] + sred[0][3];
        float a1 = sred[1][0] + sred[1][1] + sred[1][2] + sred[1][3];
        float a2 = sred[2][0] + sred[2][1] + sred[2][2] + sred[2][3];
        float a3 = sred[3][0] + sred[3][1] + sred[3][2] + sred[3][3];
        float2 r = make_float2(a0 / a2, a1 / a3);
        if (arr) g_resL[row] = r; else g_resP[row] = r;
        __threadfence();
        amLast = (atomicAdd(&g_done, 1u) == (unsigned)(NCTA - 1));
    }
    __syncthreads();

    // ---- Last CTA: combine all per-row results into the scalar loss ----
    if (amLast) {
        float acc = 0.f;
        #pragma unroll
        for (int q = 0; q < BROWS / NT; q++) {
            int r = tid + q * NT;
            float2 p = g_resP[r];
            float2 l = g_resL[r];
            float d0 = p.x - l.x;
            float d1 = p.y - l.y;
            acc += d0 * d0 + d1 * d1;
        }
        acc = warp_sum(acc);
        if (lane == 0) sred[0][wid] = acc;
        __syncthreads();
        if (tid == 0) {
            out[0] = (sred[0][0] + sred[0][1] + sred[0][2] + sred[0][3])
                   / (float)(BROWS * 2);
            g_done = 0;
        }
    }
}

extern "C" void kernel_launch(void* const* d_in, const int* in_sizes, int n_in,
                              void* d_out, int out_size) {
    const float* preds  = (const float*)d_in[0];
    const float* labels = (const float*)d_in[1];
    pv_kernel<<<NCTA, NT>>>(preds, labels, (float*)d_out);
}

// round 15
// speedup vs baseline: 1.2703x; 1.2064x over previous
#include <cuda_runtime.h>

#define TCOLS 4096
#define BROWS 4096
#define NT 128
#define NWARP 4
#define NCTA (2 * BROWS)
#define FULL 0xffffffffu

__device__ float2   g_resP[BROWS];   // {sbp, dbp} per preds row
__device__ float2   g_resL[BROWS];   // {sbp, dbp} per labels row
__device__ unsigned g_done;          // zero-init; reset by last CTA

__device__ __forceinline__ float warp_sum(float v) {
    #pragma unroll
    for (int o = 16; o; o >>= 1) v += __shfl_xor_sync(FULL, v, o);
    return v;
}

// Compress the 4 sign bits (bit 7 of each byte) into a nibble: bit k = byte k.
__device__ __forceinline__ unsigned movemask4(unsigned b) {
    return (((b >> 7) & 0x01010101u) * 0x01020408u) >> 24;
}

__global__ __launch_bounds__(NT, 8)
void pv_kernel(const float* __restrict__ preds,
               const float* __restrict__ labels,
               float* __restrict__ out) {
    __shared__ float sred[4][NWARP];
    __shared__ bool  amLast;

    const int tid  = threadIdx.x;
    const int lane = tid & 31;
    const int wid  = tid >> 5;
    const int arr  = blockIdx.x >> 12;          // 0 = preds, 1 = labels
    const int row  = blockIdx.x & (BROWS - 1);

    const float* rowp = (arr ? labels : preds) + ((size_t)row << 12);
    const int wb = wid << 10;                   // 1024 elements per warp
    const float4* g4 = (const float4*)(rowp + wb);

    // ---- Load lane's 32 elements (8 coalesced float4 groups) ----
    float v[32];
    #pragma unroll
    for (int g = 0; g < 8; g++) {
        float4 a = g4[g * 32 + lane];
        v[4*g] = a.x; v[4*g+1] = a.y; v[4*g+2] = a.z; v[4*g+3] = a.w;
    }

    // Segment-edge values (row-end centers masked off explicitly below).
    float edge_l = 0.f, edge_r = 0.f;
    if (lane == 31) edge_l = rowp[wb ? wb - 1 : 0];
    if (lane == 0)  edge_r = rowp[wb + 1024 < TCOLS ? wb + 1024 : TCOLS - 1];

    const int upidx = (lane + 31) & 31;
    const int dnidx = (lane + 1) & 31;
    const bool is31 = (lane == 31);
    const bool is0  = (lane == 0);
    const bool rowStart = is0  && (wb == 0);
    const bool rowEnd   = is31 && (wb + 1024 == TCOLS);

    // ---- Pass 1: sign-packed peak/valley detection ----
    float psum = 0.f, vsum = 0.f;
    unsigned pkm = 0, vym = 0;
    float prevw = edge_l;
    #pragma unroll
    for (int g = 0; g < 8; g++) {
        const float cx = v[4*g], cy = v[4*g+1], cz = v[4*g+2], cw = v[4*g+3];
        float bl = is31 ? prevw : cw;
        float lv = __shfl_sync(FULL, bl, upidx);     // lane i <- lane i-1
        float nx = (g < 7) ? v[4*g+4] : edge_r;
        float br = is0 ? nx : cx;
        float rv = __shfl_sync(FULL, br, dnidx);     // lane i <- lane i+1
        prevw = cw;

        const int i0 = __float_as_int(cx - lv);
        const int i1 = __float_as_int(cy - cx);
        const int i2 = __float_as_int(cz - cy);
        const int i3 = __float_as_int(cw - cz);
        const int i4 = __float_as_int(rv - cw);

        unsigned a01 = __byte_perm(i0, i1, 0x0073);
        unsigned a23 = __byte_perm(i2, i3, 0x7300);
        unsigned s   = __byte_perm(a01, a23, 0x7610);
        unsigned sn  = __byte_perm(s,   i4, 0x7321);
        unsigned pkb = ~s & sn;      // byte k bit7: d_k>0 && d_{k+1}<0
        unsigned vyb = s & ~sn;      // byte k bit7: d_k<0 && d_{k+1}>0

        if (g == 0 && rowStart) { pkb &= ~0x80u;       vyb &= ~0x80u; }
        if (g == 7 && rowEnd)   { pkb &= 0x7fffffffu;  vyb &= 0x7fffffffu; }

        // Mask build via movemask (3-4 ALU ops per mask, replaces 4 predicated updates)
        pkm |= movemask4(pkb) << (4*g);
        vym |= movemask4(vyb) << (4*g);

        // Predicated value sums only.
        if (pkb & 0x00000080u) psum += cx;
        if (vyb & 0x00000080u) vsum += cx;
        if (pkb & 0x00008000u) psum += cy;
        if (vyb & 0x00008000u) vsum += cy;
        if (pkb & 0x00800000u) psum += cz;
        if (vyb & 0x00800000u) vsum += cz;
        if (pkb & 0x80000000u) psum += cw;
        if (vyb & 0x80000000u) vsum += cw;
    }

    psum = warp_sum(psum);
    vsum = warp_sum(vsum);
    int pcnt = __reduce_add_sync(FULL, __popc(pkm));
    int vcnt = __reduce_add_sync(FULL, __popc(vym));
    if (lane == 0) {
        sred[0][wid] = psum;
        sred[1][wid] = vsum;
        sred[2][wid] = (float)pcnt;
        sred[3][wid] = (float)vcnt;
    }
    __syncthreads();
    const float pm = (sred[0][0] + sred[0][1] + sred[0][2] + sred[0][3])
                   / (sred[2][0] + sred[2][1] + sred[2][2] + sred[2][3]);
    const float vm = (sred[1][0] + sred[1][1] + sred[1][2] + sred[1][3])
                   / (sred[3][0] + sred[3][1] + sred[3][2] + sred[3][3]);
    __syncthreads();   // sred reuse

    // ---- Pass 2: thresholded masked means, registers only; float counts ----
    float s0 = 0.f, s1 = 0.f, c0 = 0.f, c1 = 0.f;
    #pragma unroll
    for (int k = 0; k < 32; k++) {
        const unsigned bit = 1u << k;
        if ((pkm & bit) && v[k] >= pm) { s0 += v[k]; c0 += 1.f; }
        if ((vym & bit) && v[k] <= vm) { s1 += v[k]; c1 += 1.f; }
    }
    s0 = warp_sum(s0);
    s1 = warp_sum(s1);
    c0 = warp_sum(c0);
    c1 = warp_sum(c1);
    if (lane == 0) {
        sred[0][wid] = s0;
        sred[1][wid] = s1;
        sred[2][wid] = c0;
        sred[3][wid] = c1;
    }
    __syncthreads();

    if (tid == 0) {
        float a0 = sred[0][0] + sred[0][1] + sred[0][2] + sred[0][3];
        float a1 = sred[1][0] + sred[1][1] + sred[1][2] + sred[1][3];
        float a2 = sred[2][0] + sred[2][1] + sred[2][2] + sred[2][3];
        float a3 = sred[3][0] + sred[3][1] + sred[3][2] + sred[3][3];
        float2 r = make_float2(a0 / a2, a1 / a3);
        if (arr) g_resL[row] = r; else g_resP[row] = r;
        __threadfence();
        amLast = (atomicAdd(&g_done, 1u) == (unsigned)(NCTA - 1));
    }
    __syncthreads();

    // ---- Last CTA: combine all per-row results into the scalar loss ----
    if (amLast) {
        float acc = 0.f;
        #pragma unroll
        for (int q = 0; q < BROWS / NT; q++) {
            int r = tid + q * NT;
            float2 p = g_resP[r];
            float2 l = g_resL[r];
            float d0 = p.x - l.x;
            float d1 = p.y - l.y;
            acc += d0 * d0 + d1 * d1;
        }
        acc = warp_sum(acc);
        if (lane == 0) sred[0][wid] = acc;
        __syncthreads();
        if (tid == 0) {
            out[0] = (sred[0][0] + sred[0][1] + sred[0][2] + sred[0][3])
                   / (float)(BROWS * 2);
            g_done = 0;
        }
    }
}

extern "C" void kernel_launch(void* const* d_in, const int* in_sizes, int n_in,
                              void* d_out, int out_size) {
    const float* preds  = (const float*)d_in[0];
    const float* labels = (const float*)d_in[1];
    pv_kernel<<<NCTA, NT>>>(preds, labels, (float*)d_out);
}